// round 1
// baseline (speedup 1.0000x reference)
#include <cuda_runtime.h>
#include <math.h>

// Problem constants
#define NB 2
#define NC 128
#define FH 80
#define FW 80
#define HS 40            // downsampled H=W
#define NQ 1600          // HS*HS
#define NEPS 0.1152f     // 1152 * EPS
#define SCL 10.0f
#define MROWS 2048       // NC * 16 offsets

// Static scratch (allocation-free rule: __device__ globals)
__device__ float g_ds[NB*3*NC*NQ];          // downsampled [b][img: 0=l,1=r,2=m][c][q]
__device__ float g_E[NB*2*NQ];              // per-pixel channel sum of squares (l, r)
__device__ float g_ninv[NB*2*NQ];           // 1/patch-norm
__device__ float g_bufA[NB*2*NQ*NQ];        // 41.9 MB ping
__device__ float g_bufB[NB*2*NQ*NQ];        // 41.9 MB pong
__device__ float g_G[NB*2*MROWS*NQ];        // 52.4 MB paste operand
__device__ float g_T[NB*2*MROWS*NQ];        // 52.4 MB paste result

// ---------------------------------------------------------------- downsample
__global__ void k_downsample(const float* __restrict__ left,
                             const float* __restrict__ right,
                             const float* __restrict__ mid) {
    int idx = blockIdx.x * blockDim.x + threadIdx.x;
    const int total = NB*3*NC*NQ;
    if (idx >= total) return;
    int q = idx % NQ;
    int t = idx / NQ;
    int c = t % NC; t /= NC;
    int img = t % 3; int b = t / 3;
    const float* src = (img == 0) ? left : (img == 1 ? right : mid);
    int qh = q / HS, qw = q % HS;
    g_ds[idx] = src[(size_t)((b*NC + c)*FH + 2*qh)*FW + 2*qw];
}

// ------------------------------------------------- channel sum-of-squares (l,r)
__global__ void k_sumsq() {
    int idx = blockIdx.x*blockDim.x + threadIdx.x;
    const int total = NB*2*NQ;
    if (idx >= total) return;
    int q = idx % NQ; int t = idx / NQ;
    int s = t % 2; int b = t / 2;
    const float* p = g_ds + (size_t)(b*3 + s)*NC*NQ + q;
    float acc = 0.f;
    #pragma unroll 8
    for (int c = 0; c < NC; ++c) { float v = p[(size_t)c*NQ]; acc += v*v; }
    g_E[idx] = acc;
}

// -------------------------------------------------- patch norm: sqrt(3x3 sum + 1152*eps)
__global__ void k_norm() {
    int idx = blockIdx.x*blockDim.x + threadIdx.x;
    const int total = NB*2*NQ;
    if (idx >= total) return;
    int q = idx % NQ; int bs = idx / NQ;
    int qh = q/HS, qw = q%HS;
    float acc = NEPS;
    for (int di=-1; di<=1; ++di) {
        int h = qh+di; if (h < 0 || h >= HS) continue;
        for (int dj=-1; dj<=1; ++dj) {
            int w = qw+dj; if (w < 0 || w >= HS) continue;
            acc += g_E[bs*NQ + h*HS + w];
        }
    }
    g_ninv[idx] = rsqrtf(acc);
}

// ----------------------------- GEMM1: PixCorr[q,p] = sum_c L[c,q]*M[c,p]  (K=128)
// Both operands K-major ([c][pix]) -> direct tile loads, no transpose.
__global__ void k_corr() {
    int bs = blockIdx.z;
    int b = bs >> 1, s = bs & 1;
    const float* A  = g_ds + (size_t)(b*3 + s)*NC*NQ;
    const float* Bm = g_ds + (size_t)(b*3 + 2)*NC*NQ;
    float* Cout = g_bufA + (size_t)bs*NQ*NQ;
    __shared__ float As[16][64];
    __shared__ float Bs[16][64];
    int tx = threadIdx.x;
    int m0 = blockIdx.x*64, n0 = blockIdx.y*64;
    int lk = tx >> 4, lm = (tx & 15) * 4;
    int lr = tx >> 4, lc = tx & 15;
    float acc[4][4];
    #pragma unroll
    for (int i=0;i<4;i++) {
        #pragma unroll
        for (int j=0;j<4;j++) acc[i][j] = 0.f;
    }
    for (int k0 = 0; k0 < NC; k0 += 16) {
        *(float4*)&As[lk][lm] = *(const float4*)&A [(size_t)(k0+lk)*NQ + m0 + lm];
        *(float4*)&Bs[lk][lm] = *(const float4*)&Bm[(size_t)(k0+lk)*NQ + n0 + lm];
        __syncthreads();
        #pragma unroll
        for (int kk = 0; kk < 16; ++kk) {
            float4 av = *(const float4*)&As[kk][lr*4];
            float4 bv = *(const float4*)&Bs[kk][lc*4];
            float a[4] = {av.x, av.y, av.z, av.w};
            float bb[4] = {bv.x, bv.y, bv.z, bv.w};
            #pragma unroll
            for (int i=0;i<4;i++) {
                #pragma unroll
                for (int j=0;j<4;j++) acc[i][j] += a[i]*bb[j];
            }
        }
        __syncthreads();
    }
    #pragma unroll
    for (int i=0;i<4;i++) {
        float4 v = make_float4(acc[i][0],acc[i][1],acc[i][2],acc[i][3]);
        *(float4*)&Cout[(size_t)(m0+lr*4+i)*NQ + n0 + lc*4] = v;
    }
}

// -------- patch 3x3 diagonal sum (2D bounds on BOTH q and p) + row normalization
__global__ void k_patchsum() {
    long long idx = (long long)blockIdx.x*blockDim.x + threadIdx.x;
    const long long total = (long long)NB*2*NQ*NQ;
    if (idx >= total) return;
    int p = (int)(idx % NQ);
    long long t = idx / NQ;
    int q = (int)(t % NQ);
    int bs = (int)(t / NQ);
    int qh=q/HS, qw=q%HS, ph=p/HS, pw=p%HS;
    const float* Cm = g_bufA + (size_t)bs*NQ*NQ;
    float acc = 0.f;
    #pragma unroll
    for (int di=-1; di<=1; ++di) {
        if (qh+di < 0 || qh+di >= HS || ph+di < 0 || ph+di >= HS) continue;
        #pragma unroll
        for (int dj=-1; dj<=1; ++dj) {
            if (qw+dj < 0 || qw+dj >= HS || pw+dj < 0 || pw+dj >= HS) continue;
            int sh = di*HS + dj;
            acc += Cm[(size_t)(q+sh)*NQ + (p+sh)];
        }
    }
    g_bufB[idx] = acc * g_ninv[bs*NQ + q];
}

// ---------------- fuse pass 1: diagonal 3-sum on flattened indices (bufB -> bufA)
__global__ void k_fuse1() {
    long long idx = (long long)blockIdx.x*blockDim.x + threadIdx.x;
    const long long total = (long long)NB*2*NQ*NQ;
    if (idx >= total) return;
    int p = (int)(idx % NQ);
    long long t = idx / NQ;
    int q = (int)(t % NQ);
    int bs = (int)(t / NQ);
    const float* S = g_bufB + (size_t)bs*NQ*NQ;
    float acc = S[(size_t)q*NQ + p];
    if (q > 0      && p > 0     ) acc += S[(size_t)(q-1)*NQ + (p-1)];
    if (q < NQ-1   && p < NQ-1  ) acc += S[(size_t)(q+1)*NQ + (p+1)];
    g_bufA[idx] = acc;
}

// transpose-flatten involution: (h,w) <-> (w,h) on flattened index
__device__ __forceinline__ int tflat(int q) { return (q % HS) * HS + q / HS; }

// ---------------- fuse pass 2: diagonal 3-sum on transposed flatten (bufA -> bufB)
__global__ void k_fuse2() {
    long long idx = (long long)blockIdx.x*blockDim.x + threadIdx.x;
    const long long total = (long long)NB*2*NQ*NQ;
    if (idx >= total) return;
    int p = (int)(idx % NQ);
    long long t = idx / NQ;
    int q = (int)(t % NQ);
    int bs = (int)(t / NQ);
    const float* F = g_bufA + (size_t)bs*NQ*NQ;
    int a = tflat(q), bb = tflat(p);
    float acc = F[(size_t)q*NQ + p];
    if (a > 0    && bb > 0   ) acc += F[(size_t)tflat(a-1)*NQ + tflat(bb-1)];
    if (a < NQ-1 && bb < NQ-1) acc += F[(size_t)tflat(a+1)*NQ + tflat(bb+1)];
    g_bufB[idx] = acc;
}

// --------------- softmax over q (rows) for each column p  (bufB -> bufA = attn)
__global__ void k_softmax() {
    int bs = blockIdx.y;
    int p0 = blockIdx.x * 64;
    const float* F = g_bufB + (size_t)bs*NQ*NQ;
    float* O = g_bufA + (size_t)bs*NQ*NQ;
    int px = threadIdx.x & 63;
    int qy = threadIdx.x >> 6;        // 0..3
    int p = p0 + px;
    __shared__ float red[4][64];
    float mx = -3.4e38f;
    for (int q = qy; q < NQ; q += 4) mx = fmaxf(mx, F[(size_t)q*NQ + p]);
    red[qy][px] = mx;
    __syncthreads();
    mx = fmaxf(fmaxf(red[0][px], red[1][px]), fmaxf(red[2][px], red[3][px]));
    __syncthreads();
    float sm = 0.f;
    for (int q = qy; q < NQ; q += 4) {
        float e = expf(SCL * (F[(size_t)q*NQ + p] - mx));
        O[(size_t)q*NQ + p] = e;
        sm += e;
    }
    red[qy][px] = sm;
    __syncthreads();
    float inv = 1.0f / (red[0][px] + red[1][px] + red[2][px] + red[3][px]);
    for (int q = qy; q < NQ; q += 4) O[(size_t)q*NQ + p] *= inv;
}

// --------------- build paste operand G[c*16+(dy+1)*4+(dx+1)][q] = raw[2qh+dy, 2qw+dx]
__global__ void k_buildG(const float* __restrict__ raw_left,
                         const float* __restrict__ raw_right) {
    int idx = blockIdx.x*blockDim.x + threadIdx.x;
    const int total = NB*2*MROWS*NQ;
    if (idx >= total) return;
    int q = idx % NQ;
    int t = idx / NQ;
    int m = t % MROWS;
    int bs = t / MROWS;
    int b = bs >> 1, s = bs & 1;
    int c = m >> 4;
    int o = m & 15;
    int dy = (o >> 2) - 1, dx = (o & 3) - 1;
    int y = 2*(q/HS) + dy, x = 2*(q%HS) + dx;
    const float* raw = s ? raw_right : raw_left;
    float v = 0.f;
    if (y >= 0 && y < FH && x >= 0 && x < FW)
        v = raw[(size_t)((b*NC + c)*FH + y)*FW + x];
    g_G[idx] = v;
}

// ------------- GEMM2: T[m,p] = sum_q G[m,q] * attn[q,p]   (2048 x 1600 x 1600)
__global__ void k_gemm2() {
    int bs = blockIdx.z;
    const float* G  = g_G   + (size_t)bs*MROWS*NQ;
    const float* Am = g_bufA + (size_t)bs*NQ*NQ;     // attn [q][p]
    float* T = g_T + (size_t)bs*MROWS*NQ;
    __shared__ float As[16][64];
    __shared__ float Bs[16][64];
    int tx = threadIdx.x;
    int m0 = blockIdx.x*64, n0 = blockIdx.y*64;
    int lmA = tx & 63, lk4 = tx >> 6;       // A tile: transpose load
    int lkB = tx >> 4, lnB = (tx & 15)*4;   // B tile: direct
    int lr = tx >> 4, lc = tx & 15;
    float acc[4][4];
    #pragma unroll
    for (int i=0;i<4;i++) {
        #pragma unroll
        for (int j=0;j<4;j++) acc[i][j] = 0.f;
    }
    for (int k0 = 0; k0 < NQ; k0 += 16) {
        float4 ga = *(const float4*)&G[(size_t)(m0+lmA)*NQ + k0 + lk4*4];
        As[lk4*4+0][lmA] = ga.x;
        As[lk4*4+1][lmA] = ga.y;
        As[lk4*4+2][lmA] = ga.z;
        As[lk4*4+3][lmA] = ga.w;
        *(float4*)&Bs[lkB][lnB] = *(const float4*)&Am[(size_t)(k0+lkB)*NQ + n0 + lnB];
        __syncthreads();
        #pragma unroll
        for (int kk = 0; kk < 16; ++kk) {
            float4 av = *(const float4*)&As[kk][lr*4];
            float4 bv = *(const float4*)&Bs[kk][lc*4];
            float a[4] = {av.x, av.y, av.z, av.w};
            float bb[4] = {bv.x, bv.y, bv.z, bv.w};
            #pragma unroll
            for (int i=0;i<4;i++) {
                #pragma unroll
                for (int j=0;j<4;j++) acc[i][j] += a[i]*bb[j];
            }
        }
        __syncthreads();
    }
    #pragma unroll
    for (int i=0;i<4;i++) {
        float4 v = make_float4(acc[i][0],acc[i][1],acc[i][2],acc[i][3]);
        *(float4*)&T[(size_t)(m0+lr*4+i)*NQ + n0 + lc*4] = v;
    }
}

// ------------- gather epilogue + cosine-window blend -> output (2,128,80,80)
__global__ void k_combine(float* __restrict__ out) {
    int idx = blockIdx.x*blockDim.x + threadIdx.x;
    const int total = NB*NC*FH*FW;
    if (idx >= total) return;
    int X = idx % FW; int t = idx / FW;
    int Y = t % FH; t /= FH;
    int c = t % NC; int b = t / NC;

    int dys[2], hh[2]; int ny = 0;
    if ((Y & 1) == 0) {
        dys[ny] = 0; hh[ny] = Y >> 1; ny++;
        if (Y >= 2) { dys[ny] = 2; hh[ny] = (Y-2) >> 1; ny++; }
    } else {
        dys[ny] = 1; hh[ny] = (Y-1) >> 1; ny++;
        if (Y <= 2*HS - 3) { dys[ny] = -1; hh[ny] = (Y+1) >> 1; ny++; }
    }
    int dxs[2], ww[2]; int nx = 0;
    if ((X & 1) == 0) {
        dxs[nx] = 0; ww[nx] = X >> 1; nx++;
        if (X >= 2) { dxs[nx] = 2; ww[nx] = (X-2) >> 1; nx++; }
    } else {
        dxs[nx] = 1; ww[nx] = (X-1) >> 1; nx++;
        if (X <= 2*HS - 3) { dxs[nx] = -1; ww[nx] = (X+1) >> 1; nx++; }
    }

    const float PI = 3.14159265358979323846f;
    float wl = 0.5f*(1.f + cosf(PI * (float)X        / (float)(FW-1)));
    float wr = 0.5f*(1.f + cosf(PI * (float)(FW-1-X) / (float)(FW-1)));

    float res = 0.f;
    for (int s = 0; s < 2; ++s) {
        const float* T = g_T + (size_t)(b*2 + s)*MROWS*NQ;
        float acc = 0.f;
        for (int iy = 0; iy < ny; ++iy) {
            for (int ix = 0; ix < nx; ++ix) {
                int m = c*16 + (dys[iy]+1)*4 + (dxs[ix]+1);
                acc += T[(size_t)m*NQ + hh[iy]*HS + ww[ix]];
            }
        }
        res += (s == 0 ? wl : wr) * 0.25f * acc;
    }
    out[idx] = res;
}

// ------------------------------------------------------------------ launcher
extern "C" void kernel_launch(void* const* d_in, const int* in_sizes, int n_in,
                              void* d_out, int out_size) {
    const float* left      = (const float*)d_in[0];
    const float* right     = (const float*)d_in[1];
    const float* mid       = (const float*)d_in[2];
    const float* raw_left  = (const float*)d_in[3];
    const float* raw_right = (const float*)d_in[4];
    float* outp = (float*)d_out;

    int t1 = NB*3*NC*NQ;
    k_downsample<<<(t1+255)/256, 256>>>(left, right, mid);
    int t2 = NB*2*NQ;
    k_sumsq<<<(t2+127)/128, 128>>>();
    k_norm<<<(t2+127)/128, 128>>>();

    dim3 gc(NQ/64, NQ/64, NB*2);
    k_corr<<<gc, 256>>>();

    long long tp = (long long)NB*2*NQ*NQ;
    int nbElem = (int)((tp + 255) / 256);
    k_patchsum<<<nbElem, 256>>>();
    k_fuse1<<<nbElem, 256>>>();
    k_fuse2<<<nbElem, 256>>>();

    k_softmax<<<dim3(NQ/64, NB*2), 256>>>();

    int tg = NB*2*MROWS*NQ;
    k_buildG<<<(tg+255)/256, 256>>>(raw_left, raw_right);

    dim3 gg(MROWS/64, NQ/64, NB*2);
    k_gemm2<<<gg, 256>>>();

    int to = NB*NC*FH*FW;
    k_combine<<<(to+255)/256, 256>>>(outp);
}

// round 2
// speedup vs baseline: 1.1433x; 1.1433x over previous
#include <cuda_runtime.h>
#include <math.h>

// Problem constants
#define NB 2
#define NC 128
#define FH 80
#define FW 80
#define HS 40            // downsampled H=W
#define NQ 1600          // HS*HS
#define NEPS 0.1152f     // 1152 * EPS
#define SCL 10.0f
#define MROWS 2048       // NC * 16 offsets

// SGEMM tile config
#define BM 128
#define BN 128
#define BKD 8
#define TM 8
#define TN 8

// Static scratch (allocation-free rule: __device__ globals)
__device__ float g_ds[NB*3*NC*NQ];          // downsampled [b][img: 0=l,1=r,2=m][c][q]
__device__ float g_E[NB*2*NQ];              // per-pixel channel sum of squares (l, r)
__device__ float g_ninv[NB*2*NQ];           // 1/patch-norm
__device__ float g_bufA[NB*2*NQ*NQ];        // 41.9 MB ping
__device__ float g_bufB[NB*2*NQ*NQ];        // 41.9 MB pong
__device__ float g_G[NB*2*NQ*MROWS];        // 52.4 MB paste operand, [bs][q][m] (K-major)
__device__ float g_T[NB*2*MROWS*NQ];        // 52.4 MB paste result  [bs][m][p]

// ---------------------------------------------------------------- downsample
__global__ void k_downsample(const float* __restrict__ left,
                             const float* __restrict__ right,
                             const float* __restrict__ mid) {
    int idx = blockIdx.x * blockDim.x + threadIdx.x;
    const int total = NB*3*NC*NQ;
    if (idx >= total) return;
    int q = idx % NQ;
    int t = idx / NQ;
    int c = t % NC; t /= NC;
    int img = t % 3; int b = t / 3;
    const float* src = (img == 0) ? left : (img == 1 ? right : mid);
    int qh = q / HS, qw = q % HS;
    g_ds[idx] = src[(size_t)((b*NC + c)*FH + 2*qh)*FW + 2*qw];
}

// ------------------------------------------------- channel sum-of-squares (l,r)
__global__ void k_sumsq() {
    int idx = blockIdx.x*blockDim.x + threadIdx.x;
    const int total = NB*2*NQ;
    if (idx >= total) return;
    int q = idx % NQ; int t = idx / NQ;
    int s = t % 2; int b = t / 2;
    const float* p = g_ds + (size_t)(b*3 + s)*NC*NQ + q;
    float acc = 0.f;
    #pragma unroll 8
    for (int c = 0; c < NC; ++c) { float v = p[(size_t)c*NQ]; acc += v*v; }
    g_E[idx] = acc;
}

// -------------------------------------------------- patch norm: sqrt(3x3 sum + 1152*eps)
__global__ void k_norm() {
    int idx = blockIdx.x*blockDim.x + threadIdx.x;
    const int total = NB*2*NQ;
    if (idx >= total) return;
    int q = idx % NQ; int bs = idx / NQ;
    int qh = q/HS, qw = q%HS;
    float acc = NEPS;
    for (int di=-1; di<=1; ++di) {
        int h = qh+di; if (h < 0 || h >= HS) continue;
        for (int dj=-1; dj<=1; ++dj) {
            int w = qw+dj; if (w < 0 || w >= HS) continue;
            acc += g_E[bs*NQ + h*HS + w];
        }
    }
    g_ninv[idx] = rsqrtf(acc);
}

// ---------------------------------------------------------------- SGEMM core
// C[M,N] = A^T * B where A is [K][M] (lda), B is [K][N] (ldb), C row stride ldc.
// 128x128x8 tiles, 8x8 per thread, 256 threads, register double buffering.
__device__ __forceinline__ void sgemm_body(
    const float* __restrict__ A,
    const float* __restrict__ B,
    float* __restrict__ C,
    int M, int N, int K, int lda, int ldb, int ldc)
{
    __shared__ float As[2][BKD][BM];
    __shared__ float Bs[2][BKD][BN];
    const int t = threadIdx.x;
    const int m0 = blockIdx.x * BM;
    const int n0 = blockIdx.y * BN;
    const int lrow = t >> 5;             // 0..7 (k-row within tile)
    const int lcol = (t & 31) << 2;      // 0..124
    const bool pA = (m0 + lcol) < M;
    const bool pB = (n0 + lcol) < N;
    const float* Aptr = A + (size_t)lrow * lda + m0 + lcol;
    const float* Bptr = B + (size_t)lrow * ldb + n0 + lcol;
    const int tr = t >> 4, tc = t & 15;

    const float4 fz = make_float4(0.f,0.f,0.f,0.f);
    float4 ra = pA ? *(const float4*)Aptr : fz;
    float4 rb = pB ? *(const float4*)Bptr : fz;
    *(float4*)&As[0][lrow][lcol] = ra;
    *(float4*)&Bs[0][lrow][lcol] = rb;
    __syncthreads();

    float acc[TM][TN];
    #pragma unroll
    for (int i=0;i<TM;i++)
        #pragma unroll
        for (int j=0;j<TN;j++) acc[i][j] = 0.f;

    const int ntiles = K / BKD;
    for (int it = 0; it < ntiles; ++it) {
        const int buf = it & 1;
        if (it + 1 < ntiles) {
            ra = pA ? *(const float4*)(Aptr + (size_t)BKD*lda) : fz;
            rb = pB ? *(const float4*)(Bptr + (size_t)BKD*ldb) : fz;
        }
        #pragma unroll
        for (int kk = 0; kk < BKD; ++kk) {
            float a[TM], b[TN];
            *(float4*)&a[0] = *(const float4*)&As[buf][kk][tr*TM];
            *(float4*)&a[4] = *(const float4*)&As[buf][kk][tr*TM+4];
            *(float4*)&b[0] = *(const float4*)&Bs[buf][kk][tc*TN];
            *(float4*)&b[4] = *(const float4*)&Bs[buf][kk][tc*TN+4];
            #pragma unroll
            for (int i=0;i<TM;i++)
                #pragma unroll
                for (int j=0;j<TN;j++) acc[i][j] += a[i]*b[j];
        }
        if (it + 1 < ntiles) {
            *(float4*)&As[buf^1][lrow][lcol] = ra;
            *(float4*)&Bs[buf^1][lrow][lcol] = rb;
            __syncthreads();
            Aptr += (size_t)BKD*lda;
            Bptr += (size_t)BKD*ldb;
        }
    }

    #pragma unroll
    for (int i = 0; i < TM; ++i) {
        int m = m0 + tr*TM + i;
        if (m < M) {
            #pragma unroll
            for (int j = 0; j < TN; j += 4) {
                int n = n0 + tc*TN + j;
                if (n < N) {
                    float4 v = make_float4(acc[i][j], acc[i][j+1], acc[i][j+2], acc[i][j+3]);
                    *(float4*)&C[(size_t)m*ldc + n] = v;
                }
            }
        }
    }
}

// GEMM1: PixCorr[q,p] = sum_c L[c,q]*M[c,p]
__global__ void __launch_bounds__(256, 2) k_gemm1() {
    int bs = blockIdx.z;
    int b = bs >> 1, s = bs & 1;
    sgemm_body(g_ds + (size_t)(b*3 + s)*NC*NQ,
               g_ds + (size_t)(b*3 + 2)*NC*NQ,
               g_bufA + (size_t)bs*NQ*NQ,
               NQ, NQ, NC, NQ, NQ, NQ);
}

// GEMM2: T[m,p] = sum_q Gt[q,m] * attn[q,p]
__global__ void __launch_bounds__(256, 2) k_gemm2() {
    int bs = blockIdx.z;
    sgemm_body(g_G + (size_t)bs*NQ*MROWS,
               g_bufA + (size_t)bs*NQ*NQ,
               g_T + (size_t)bs*MROWS*NQ,
               MROWS, NQ, NQ, MROWS, NQ, NQ);
}

// -------- patch 3x3 diagonal sum (2D bounds on BOTH q and p) + row normalization
__global__ void k_patchsum() {
    long long idx = (long long)blockIdx.x*blockDim.x + threadIdx.x;
    const long long total = (long long)NB*2*NQ*NQ;
    if (idx >= total) return;
    int p = (int)(idx % NQ);
    long long t = idx / NQ;
    int q = (int)(t % NQ);
    int bs = (int)(t / NQ);
    int qh=q/HS, qw=q%HS, ph=p/HS, pw=p%HS;
    const float* Cm = g_bufA + (size_t)bs*NQ*NQ;
    float acc = 0.f;
    #pragma unroll
    for (int di=-1; di<=1; ++di) {
        if (qh+di < 0 || qh+di >= HS || ph+di < 0 || ph+di >= HS) continue;
        #pragma unroll
        for (int dj=-1; dj<=1; ++dj) {
            if (qw+dj < 0 || qw+dj >= HS || pw+dj < 0 || pw+dj >= HS) continue;
            int sh = di*HS + dj;
            acc += Cm[(size_t)(q+sh)*NQ + (p+sh)];
        }
    }
    g_bufB[idx] = acc * g_ninv[bs*NQ + q];
}

// ---------------- fuse pass 1: diagonal 3-sum on flattened indices (bufB -> bufA)
__global__ void k_fuse1() {
    long long idx = (long long)blockIdx.x*blockDim.x + threadIdx.x;
    const long long total = (long long)NB*2*NQ*NQ;
    if (idx >= total) return;
    int p = (int)(idx % NQ);
    long long t = idx / NQ;
    int q = (int)(t % NQ);
    int bs = (int)(t / NQ);
    const float* S = g_bufB + (size_t)bs*NQ*NQ;
    float acc = S[(size_t)q*NQ + p];
    if (q > 0      && p > 0     ) acc += S[(size_t)(q-1)*NQ + (p-1)];
    if (q < NQ-1   && p < NQ-1  ) acc += S[(size_t)(q+1)*NQ + (p+1)];
    g_bufA[idx] = acc;
}

// transpose-flatten involution: (h,w) <-> (w,h) on flattened index
__device__ __forceinline__ int tflat(int q) { return (q % HS) * HS + q / HS; }

// ---------------- fuse pass 2: diagonal 3-sum on transposed flatten (bufA -> bufB)
__global__ void k_fuse2() {
    long long idx = (long long)blockIdx.x*blockDim.x + threadIdx.x;
    const long long total = (long long)NB*2*NQ*NQ;
    if (idx >= total) return;
    int p = (int)(idx % NQ);
    long long t = idx / NQ;
    int q = (int)(t % NQ);
    int bs = (int)(t / NQ);
    const float* F = g_bufA + (size_t)bs*NQ*NQ;
    int a = tflat(q), bb = tflat(p);
    float acc = F[(size_t)q*NQ + p];
    if (a > 0    && bb > 0   ) acc += F[(size_t)tflat(a-1)*NQ + tflat(bb-1)];
    if (a < NQ-1 && bb < NQ-1) acc += F[(size_t)tflat(a+1)*NQ + tflat(bb+1)];
    g_bufB[idx] = acc;
}

// --------------- softmax over q (rows) for each column p  (bufB -> bufA = attn)
__global__ void k_softmax() {
    int bs = blockIdx.y;
    int p0 = blockIdx.x * 64;
    const float* F = g_bufB + (size_t)bs*NQ*NQ;
    float* O = g_bufA + (size_t)bs*NQ*NQ;
    int px = threadIdx.x & 63;
    int qy = threadIdx.x >> 6;        // 0..3
    int p = p0 + px;
    __shared__ float red[4][64];
    float mx = -3.4e38f;
    for (int q = qy; q < NQ; q += 4) mx = fmaxf(mx, F[(size_t)q*NQ + p]);
    red[qy][px] = mx;
    __syncthreads();
    mx = fmaxf(fmaxf(red[0][px], red[1][px]), fmaxf(red[2][px], red[3][px]));
    __syncthreads();
    float sm = 0.f;
    for (int q = qy; q < NQ; q += 4) {
        float e = expf(SCL * (F[(size_t)q*NQ + p] - mx));
        O[(size_t)q*NQ + p] = e;
        sm += e;
    }
    red[qy][px] = sm;
    __syncthreads();
    float inv = 1.0f / (red[0][px] + red[1][px] + red[2][px] + red[3][px]);
    for (int q = qy; q < NQ; q += 4) O[(size_t)q*NQ + p] *= inv;
}

// --------------- build paste operand, TRANSPOSED for GEMM2:
// Gt[bs][q][m], m = c*16+(dy+1)*4+(dx+1), value = raw[c, 2qh+dy, 2qw+dx]
__global__ void k_buildG(const float* __restrict__ raw_left,
                         const float* __restrict__ raw_right) {
    int idx = blockIdx.x*blockDim.x + threadIdx.x;
    const int total = NB*2*NQ*MROWS;
    if (idx >= total) return;
    int m = idx % MROWS;
    int t = idx / MROWS;
    int q = t % NQ;
    int bs = t / NQ;
    int b = bs >> 1, s = bs & 1;
    int c = m >> 4;
    int o = m & 15;
    int dy = (o >> 2) - 1, dx = (o & 3) - 1;
    int y = 2*(q/HS) + dy, x = 2*(q%HS) + dx;
    const float* raw = s ? raw_right : raw_left;
    float v = 0.f;
    if (y >= 0 && y < FH && x >= 0 && x < FW)
        v = raw[(size_t)((b*NC + c)*FH + y)*FW + x];
    g_G[idx] = v;
}

// ------------- gather epilogue + cosine-window blend -> output (2,128,80,80)
__global__ void k_combine(float* __restrict__ out) {
    int idx = blockIdx.x*blockDim.x + threadIdx.x;
    const int total = NB*NC*FH*FW;
    if (idx >= total) return;
    int X = idx % FW; int t = idx / FW;
    int Y = t % FH; t /= FH;
    int c = t % NC; int b = t / NC;

    int dys[2], hh[2]; int ny = 0;
    if ((Y & 1) == 0) {
        dys[ny] = 0; hh[ny] = Y >> 1; ny++;
        if (Y >= 2) { dys[ny] = 2; hh[ny] = (Y-2) >> 1; ny++; }
    } else {
        dys[ny] = 1; hh[ny] = (Y-1) >> 1; ny++;
        if (Y <= 2*HS - 3) { dys[ny] = -1; hh[ny] = (Y+1) >> 1; ny++; }
    }
    int dxs[2], ww[2]; int nx = 0;
    if ((X & 1) == 0) {
        dxs[nx] = 0; ww[nx] = X >> 1; nx++;
        if (X >= 2) { dxs[nx] = 2; ww[nx] = (X-2) >> 1; nx++; }
    } else {
        dxs[nx] = 1; ww[nx] = (X-1) >> 1; nx++;
        if (X <= 2*HS - 3) { dxs[nx] = -1; ww[nx] = (X+1) >> 1; nx++; }
    }

    const float PI = 3.14159265358979323846f;
    float wl = 0.5f*(1.f + cosf(PI * (float)X        / (float)(FW-1)));
    float wr = 0.5f*(1.f + cosf(PI * (float)(FW-1-X) / (float)(FW-1)));

    float res = 0.f;
    for (int s = 0; s < 2; ++s) {
        const float* T = g_T + (size_t)(b*2 + s)*MROWS*NQ;
        float acc = 0.f;
        for (int iy = 0; iy < ny; ++iy) {
            for (int ix = 0; ix < nx; ++ix) {
                int m = c*16 + (dys[iy]+1)*4 + (dxs[ix]+1);
                acc += T[(size_t)m*NQ + hh[iy]*HS + ww[ix]];
            }
        }
        res += (s == 0 ? wl : wr) * 0.25f * acc;
    }
    out[idx] = res;
}

// ------------------------------------------------------------------ launcher
extern "C" void kernel_launch(void* const* d_in, const int* in_sizes, int n_in,
                              void* d_out, int out_size) {
    const float* left      = (const float*)d_in[0];
    const float* right     = (const float*)d_in[1];
    const float* mid       = (const float*)d_in[2];
    const float* raw_left  = (const float*)d_in[3];
    const float* raw_right = (const float*)d_in[4];
    float* outp = (float*)d_out;

    int t1 = NB*3*NC*NQ;
    k_downsample<<<(t1+255)/256, 256>>>(left, right, mid);
    int t2 = NB*2*NQ;
    k_sumsq<<<(t2+127)/128, 128>>>();
    k_norm<<<(t2+127)/128, 128>>>();

    dim3 g1((NQ+BM-1)/BM, (NQ+BN-1)/BN, NB*2);     // 13 x 13 x 4
    k_gemm1<<<g1, 256>>>();

    long long tp = (long long)NB*2*NQ*NQ;
    int nbElem = (int)((tp + 255) / 256);
    k_patchsum<<<nbElem, 256>>>();
    k_fuse1<<<nbElem, 256>>>();
    k_fuse2<<<nbElem, 256>>>();

    k_softmax<<<dim3(NQ/64, NB*2), 256>>>();

    int tg = NB*2*NQ*MROWS;
    k_buildG<<<(tg+255)/256, 256>>>(raw_left, raw_right);

    dim3 g2(MROWS/BM, (NQ+BN-1)/BN, NB*2);         // 16 x 13 x 4
    k_gemm2<<<g2, 256>>>();

    int to = NB*NC*FH*FW;
    k_combine<<<(to+255)/256, 256>>>(outp);
}

// round 4
// speedup vs baseline: 1.9762x; 1.7284x over previous
#include <cuda_runtime.h>
#include <math.h>
#include <stdint.h>

// Problem constants
#define NB 2
#define NC 128
#define FH 80
#define FW 80
#define HS 40            // downsampled H=W
#define NQ 1600          // HS*HS
#define NEPS 0.1152f     // 1152 * EPS
#define SCL 10.0f
#define MROWS 2048       // NC * 16 offsets

// tf32 mma GEMM2 config: CTA 128x128, K-tile 32, 8 warps (warp tile 64x32)
#define KT 32
#define G2_SMEM 65536    // 2 buffers x (16KB A + 16KB B)

// Static scratch (allocation-free rule: __device__ globals)
__device__ float g_ds[NB*3*NC*NQ];          // downsampled [b][img: 0=l,1=r,2=m][c][q]
__device__ float g_E[NB*2*NQ];              // per-pixel channel sum of squares (l, r)
__device__ float g_ninv[NB*2*NQ];           // 1/patch-norm
__device__ float g_smax[NB*2*NQ];           // softmax max per (bs,p)
__device__ float g_sinv[NB*2*NQ];           // softmax 1/sum per (bs,p)
__device__ float g_bufA[NB*2*NQ*NQ];        // 41.9 MB ping (scores / attnT)
__device__ float g_bufB[NB*2*NQ*NQ];        // 41.9 MB pong
__device__ float g_G[NB*2*MROWS*NQ];        // 52.4 MB paste operand [bs][m][q] (K-major, tf32)
__device__ float g_T[NB*2*MROWS*NQ];        // 52.4 MB paste result  [bs][m][p]

__device__ __forceinline__ float tf32_rna(float v) {
    uint32_t u;
    asm("cvt.rna.tf32.f32 %0, %1;" : "=r"(u) : "f"(v));
    return __uint_as_float(u);
}

// ---------------------------------------------------------------- downsample
__global__ void k_downsample(const float* __restrict__ left,
                             const float* __restrict__ right,
                             const float* __restrict__ mid) {
    int idx = blockIdx.x * blockDim.x + threadIdx.x;
    const int total = NB*3*NC*NQ;
    if (idx >= total) return;
    int q = idx % NQ;
    int t = idx / NQ;
    int c = t % NC; t /= NC;
    int img = t % 3; int b = t / 3;
    const float* src = (img == 0) ? left : (img == 1 ? right : mid);
    int qh = q / HS, qw = q % HS;
    g_ds[idx] = src[(size_t)((b*NC + c)*FH + 2*qh)*FW + 2*qw];
}

// ------------------------------------------------- channel sum-of-squares (l,r)
__global__ void k_sumsq() {
    int idx = blockIdx.x*blockDim.x + threadIdx.x;
    const int total = NB*2*NQ;
    if (idx >= total) return;
    int q = idx % NQ; int t = idx / NQ;
    int s = t % 2; int b = t / 2;
    const float* p = g_ds + (size_t)(b*3 + s)*NC*NQ + q;
    float acc = 0.f;
    #pragma unroll 8
    for (int c = 0; c < NC; ++c) { float v = p[(size_t)c*NQ]; acc += v*v; }
    g_E[idx] = acc;
}

// -------------------------------------------------- patch norm
__global__ void k_norm() {
    int idx = blockIdx.x*blockDim.x + threadIdx.x;
    const int total = NB*2*NQ;
    if (idx >= total) return;
    int q = idx % NQ; int bs = idx / NQ;
    int qh = q/HS, qw = q%HS;
    float acc = NEPS;
    for (int di=-1; di<=1; ++di) {
        int h = qh+di; if (h < 0 || h >= HS) continue;
        for (int dj=-1; dj<=1; ++dj) {
            int w = qw+dj; if (w < 0 || w >= HS) continue;
            acc += g_E[bs*NQ + h*HS + w];
        }
    }
    g_ninv[idx] = rsqrtf(acc);
}

// ----------------------------- GEMM1 (fp32): PixCorr[q,p] = sum_c L[c,q]*M[c,p]
// 64x64x16 tiles, 4x4 per thread (R0 tiling: measured fastest for K=128).
__global__ void k_gemm1() {
    int bs = blockIdx.z;
    int b = bs >> 1, s = bs & 1;
    const float* A  = g_ds + (size_t)(b*3 + s)*NC*NQ;
    const float* Bm = g_ds + (size_t)(b*3 + 2)*NC*NQ;
    float* Cout = g_bufA + (size_t)bs*NQ*NQ;
    __shared__ float As[16][64];
    __shared__ float Bs[16][64];
    int tx = threadIdx.x;
    int m0 = blockIdx.x*64, n0 = blockIdx.y*64;
    int lk = tx >> 4, lm = (tx & 15) * 4;
    int lr = tx >> 4, lc = tx & 15;
    float acc[4][4];
    #pragma unroll
    for (int i=0;i<4;i++)
        #pragma unroll
        for (int j=0;j<4;j++) acc[i][j] = 0.f;
    for (int k0 = 0; k0 < NC; k0 += 16) {
        *(float4*)&As[lk][lm] = *(const float4*)&A [(size_t)(k0+lk)*NQ + m0 + lm];
        *(float4*)&Bs[lk][lm] = *(const float4*)&Bm[(size_t)(k0+lk)*NQ + n0 + lm];
        __syncthreads();
        #pragma unroll
        for (int kk = 0; kk < 16; ++kk) {
            float4 av = *(const float4*)&As[kk][lr*4];
            float4 bv = *(const float4*)&Bs[kk][lc*4];
            float a[4] = {av.x, av.y, av.z, av.w};
            float bb[4] = {bv.x, bv.y, bv.z, bv.w};
            #pragma unroll
            for (int i=0;i<4;i++)
                #pragma unroll
                for (int j=0;j<4;j++) acc[i][j] += a[i]*bb[j];
        }
        __syncthreads();
    }
    #pragma unroll
    for (int i=0;i<4;i++) {
        float4 v = make_float4(acc[i][0],acc[i][1],acc[i][2],acc[i][3]);
        *(float4*)&Cout[(size_t)(m0+lr*4+i)*NQ + n0 + lc*4] = v;
    }
}

// -------- patch 3x3 diagonal sum + row normalization (bufA -> bufB)
__global__ void k_patchsum() {
    long long idx = (long long)blockIdx.x*blockDim.x + threadIdx.x;
    const long long total = (long long)NB*2*NQ*NQ;
    if (idx >= total) return;
    int p = (int)(idx % NQ);
    long long t = idx / NQ;
    int q = (int)(t % NQ);
    int bs = (int)(t / NQ);
    int qh=q/HS, qw=q%HS, ph=p/HS, pw=p%HS;
    const float* Cm = g_bufA + (size_t)bs*NQ*NQ;
    float acc = 0.f;
    #pragma unroll
    for (int di=-1; di<=1; ++di) {
        if (qh+di < 0 || qh+di >= HS || ph+di < 0 || ph+di >= HS) continue;
        #pragma unroll
        for (int dj=-1; dj<=1; ++dj) {
            if (qw+dj < 0 || qw+dj >= HS || pw+dj < 0 || pw+dj >= HS) continue;
            int sh = di*HS + dj;
            acc += Cm[(size_t)(q+sh)*NQ + (p+sh)];
        }
    }
    g_bufB[idx] = acc * g_ninv[bs*NQ + q];
}

// ---------------- fuse pass 1 (bufB -> bufA)
__global__ void k_fuse1() {
    long long idx = (long long)blockIdx.x*blockDim.x + threadIdx.x;
    const long long total = (long long)NB*2*NQ*NQ;
    if (idx >= total) return;
    int p = (int)(idx % NQ);
    long long t = idx / NQ;
    int q = (int)(t % NQ);
    int bs = (int)(t / NQ);
    const float* S = g_bufB + (size_t)bs*NQ*NQ;
    float acc = S[(size_t)q*NQ + p];
    if (q > 0      && p > 0     ) acc += S[(size_t)(q-1)*NQ + (p-1)];
    if (q < NQ-1   && p < NQ-1  ) acc += S[(size_t)(q+1)*NQ + (p+1)];
    g_bufA[idx] = acc;
}

__device__ __forceinline__ int tflat(int q) { return (q % HS) * HS + q / HS; }

// ---------------- fuse pass 2 (bufA -> bufB)
__global__ void k_fuse2() {
    long long idx = (long long)blockIdx.x*blockDim.x + threadIdx.x;
    const long long total = (long long)NB*2*NQ*NQ;
    if (idx >= total) return;
    int p = (int)(idx % NQ);
    long long t = idx / NQ;
    int q = (int)(t % NQ);
    int bs = (int)(t / NQ);
    const float* F = g_bufA + (size_t)bs*NQ*NQ;
    int a = tflat(q), bb = tflat(p);
    float acc = F[(size_t)q*NQ + p];
    if (a > 0    && bb > 0   ) acc += F[(size_t)tflat(a-1)*NQ + tflat(bb-1)];
    if (a < NQ-1 && bb < NQ-1) acc += F[(size_t)tflat(a+1)*NQ + tflat(bb+1)];
    g_bufB[idx] = acc;
}

// --------------- softmax stats: per (bs,p) max over q and 1/sum(exp)
__global__ void k_softmax_stats() {
    int bs = blockIdx.y;
    int p0 = blockIdx.x * 64;
    const float* F = g_bufB + (size_t)bs*NQ*NQ;
    int px = threadIdx.x & 63;
    int qy = threadIdx.x >> 6;        // 0..3
    int p = p0 + px;
    __shared__ float red[4][64];
    float mx = -3.4e38f;
    for (int q = qy; q < NQ; q += 4) mx = fmaxf(mx, F[(size_t)q*NQ + p]);
    red[qy][px] = mx;
    __syncthreads();
    mx = fmaxf(fmaxf(red[0][px], red[1][px]), fmaxf(red[2][px], red[3][px]));
    __syncthreads();
    float sm = 0.f;
    for (int q = qy; q < NQ; q += 4) sm += expf(SCL * (F[(size_t)q*NQ + p] - mx));
    red[qy][px] = sm;
    __syncthreads();
    if (qy == 0) {
        g_smax[bs*NQ + p] = mx;
        g_sinv[bs*NQ + p] = 1.0f / (red[0][px] + red[1][px] + red[2][px] + red[3][px]);
    }
}

// --------------- attnT: transposed, normalized, tf32-rounded attn (bufB -> bufA)
// attnT[bs][p][q] = tf32( exp(SCL*(F[q][p]-mx[p])) * inv[p] )
__global__ void k_attnT() {
    __shared__ float tile[32][33];
    int bs = blockIdx.z;
    int q0 = blockIdx.x * 32, p0 = blockIdx.y * 32;
    const float* F = g_bufB + (size_t)bs*NQ*NQ;
    float* O = g_bufA + (size_t)bs*NQ*NQ;
    int tx = threadIdx.x, ty = threadIdx.y;  // 32 x 8
    for (int r = ty; r < 32; r += 8)
        tile[r][tx] = F[(size_t)(q0+r)*NQ + p0 + tx];
    __syncthreads();
    for (int r = ty; r < 32; r += 8) {
        int p = p0 + r;
        float e = expf(SCL * (tile[tx][r] - g_smax[bs*NQ + p])) * g_sinv[bs*NQ + p];
        O[(size_t)p*NQ + q0 + tx] = tf32_rna(e);
    }
}

// --------------- build paste operand G[bs][m][q] (K-major over q), tf32-rounded
__global__ void k_buildG(const float* __restrict__ raw_left,
                         const float* __restrict__ raw_right) {
    int idx = blockIdx.x*blockDim.x + threadIdx.x;
    const int total = NB*2*MROWS*NQ;
    if (idx >= total) return;
    int q = idx % NQ;
    int t = idx / NQ;
    int m = t % MROWS;
    int bs = t / MROWS;
    int b = bs >> 1, s = bs & 1;
    int c = m >> 4;
    int o = m & 15;
    int dy = (o >> 2) - 1, dx = (o & 3) - 1;
    int y = 2*(q/HS) + dy, x = 2*(q%HS) + dx;
    const float* raw = s ? raw_right : raw_left;
    float v = 0.f;
    if (y >= 0 && y < FH && x >= 0 && x < FW)
        v = raw[(size_t)((b*NC + c)*FH + y)*FW + x];
    g_G[idx] = tf32_rna(v);
}

// ------------- GEMM2 (mma.sync tf32): T[m,p] = sum_q G[m,q] * attnT[p,q]
// CTA 128x128, K-tile 32, 8 warps (2m x 4n), warp tile 64x32,
// fragment-permuted double-buffered smem, one syncthreads per K-tile.
__device__ __forceinline__ void mma_tf32(float* c, const float4& af, const float2& bf) {
    // smem slot order (a0,a2,a1,a3) -> mma operands a0=x, a1=z, a2=y, a3=w
    asm volatile(
        "mma.sync.aligned.m16n8k8.row.col.f32.tf32.tf32.f32 "
        "{%0,%1,%2,%3}, {%4,%5,%6,%7}, {%8,%9}, {%0,%1,%2,%3};"
        : "+f"(c[0]), "+f"(c[1]), "+f"(c[2]), "+f"(c[3])
        : "r"(__float_as_uint(af.x)), "r"(__float_as_uint(af.z)),
          "r"(__float_as_uint(af.y)), "r"(__float_as_uint(af.w)),
          "r"(__float_as_uint(bf.x)), "r"(__float_as_uint(bf.y)));
}

__global__ void __launch_bounds__(256) k_gemm2t() {
    extern __shared__ char smx[];
    const int bs = blockIdx.z;
    const float* __restrict__ Gm = g_G + (size_t)bs*MROWS*NQ;     // [m][q]
    const float* __restrict__ Bm = g_bufA + (size_t)bs*NQ*NQ;     // attnT [p][q]
    float* __restrict__ Tm = g_T + (size_t)bs*MROWS*NQ;
    const int m0 = blockIdx.x * 128, n0 = blockIdx.y * 128;
    const int t = threadIdx.x;
    const int lane = t & 31, wid = t >> 5;
    const int wm = wid & 1, wn = wid >> 1;     // warp grid 2(m) x 4(n)

    // per-thread global staging: 2 units, each unit = (row, s) -> 8 consecutive k
    int row_[2], s_[2];
    {
        int u0 = t;        row_[0] = u0 >> 2; s_[0] = u0 & 3;
        int u1 = 256 + t;  row_[1] = u1 >> 2; s_[1] = u1 & 3;
    }
    float4 gaA[2][2], gaB[2][2];

    float acc[4][4][4];
    #pragma unroll
    for (int i=0;i<4;i++)
        #pragma unroll
        for (int j=0;j<4;j++)
            #pragma unroll
            for (int k=0;k<4;k++) acc[i][j][k] = 0.f;

    // prime: load tile 0
    #pragma unroll
    for (int rep = 0; rep < 2; ++rep) {
        int row = row_[rep], s = s_[rep];
        const float* gp = &Gm[(size_t)(m0+row)*NQ + 8*s];
        gaA[rep][0] = *(const float4*)gp;
        gaA[rep][1] = *(const float4*)(gp + 4);
        int p = n0 + row;
        if (p < NQ) {
            const float* bp = &Bm[(size_t)p*NQ + 8*s];
            gaB[rep][0] = *(const float4*)bp;
            gaB[rep][1] = *(const float4*)(bp + 4);
        } else {
            gaB[rep][0] = gaB[rep][1] = make_float4(0.f,0.f,0.f,0.f);
        }
    }

    const int NTILES = NQ / KT;   // 50
    for (int it = 0; it < NTILES; ++it) {
        char* base = smx + (it & 1) * 32768;
        float* Asl = (float*)base;             // A perm: [(s*8+mt)*32 + l] float4 slots
        float* Bsl = (float*)(base + 16384);   // B perm: [(s*16+nt)*32 + l] float2 slots

        // scatter staged regs into fragment-permuted smem (STS.64 each)
        #pragma unroll
        for (int rep = 0; rep < 2; ++rep) {
            int row = row_[rep], s = s_[rep];
            int mt = row >> 4;
            int rb = (row >> 3) & 1;
            int l4 = (row & 7) * 4;
            int nt = row >> 3;
            float aA0[4] = {gaA[rep][0].x, gaA[rep][0].y, gaA[rep][0].z, gaA[rep][0].w};
            float aA1[4] = {gaA[rep][1].x, gaA[rep][1].y, gaA[rep][1].z, gaA[rep][1].w};
            float aB0[4] = {gaB[rep][0].x, gaB[rep][0].y, gaB[rep][0].z, gaB[rep][0].w};
            float aB1[4] = {gaB[rep][1].x, gaB[rep][1].y, gaB[rep][1].z, gaB[rep][1].w};
            float* abase = Asl + ((s*8 + mt)*32)*4 + rb*2;
            float* bbase = Bsl + ((s*16 + nt)*32)*2;
            #pragma unroll
            for (int i = 0; i < 4; ++i) {
                *(float2*)(abase + (l4 + i)*4) = make_float2(aA0[i], aA1[i]);
                *(float2*)(bbase + (l4 + i)*2) = make_float2(aB0[i], aB1[i]);
            }
        }
        __syncthreads();

        // prefetch next tile's global data (overlaps with mma below)
        if (it + 1 < NTILES) {
            int k0n = (it + 1) * KT;
            #pragma unroll
            for (int rep = 0; rep < 2; ++rep) {
                int row = row_[rep], s = s_[rep];
                const float* gp = &Gm[(size_t)(m0+row)*NQ + k0n + 8*s];
                gaA[rep][0] = *(const float4*)gp;
                gaA[rep][1] = *(const float4*)(gp + 4);
                int p = n0 + row;
                if (p < NQ) {
                    const float* bp = &Bm[(size_t)p*NQ + k0n + 8*s];
                    gaB[rep][0] = *(const float4*)bp;
                    gaB[rep][1] = *(const float4*)(bp + 4);
                } else {
                    gaB[rep][0] = gaB[rep][1] = make_float4(0.f,0.f,0.f,0.f);
                }
            }
        }

        // consume 4 k-steps
        #pragma unroll
        for (int s = 0; s < 4; ++s) {
            float4 af[4]; float2 bf[4];
            #pragma unroll
            for (int mt = 0; mt < 4; ++mt)
                af[mt] = ((const float4*)Asl)[(s*8 + wm*4 + mt)*32 + lane];
            #pragma unroll
            for (int nt = 0; nt < 4; ++nt)
                bf[nt] = ((const float2*)Bsl)[(s*16 + wn*4 + nt)*32 + lane];
            #pragma unroll
            for (int mt = 0; mt < 4; ++mt)
                #pragma unroll
                for (int nt = 0; nt < 4; ++nt)
                    mma_tf32(acc[mt][nt], af[mt], bf[nt]);
        }
    }

    // epilogue
    #pragma unroll
    for (int mt = 0; mt < 4; ++mt) {
        int m = m0 + wm*64 + mt*16 + (lane >> 2);
        #pragma unroll
        for (int nt = 0; nt < 4; ++nt) {
            int n = n0 + wn*32 + nt*8 + 2*(lane & 3);
            if (n < NQ) {
                *(float2*)&Tm[(size_t)m*NQ + n]     = make_float2(acc[mt][nt][0], acc[mt][nt][1]);
                *(float2*)&Tm[(size_t)(m+8)*NQ + n] = make_float2(acc[mt][nt][2], acc[mt][nt][3]);
            }
        }
    }
}

// ------------- gather epilogue + cosine-window blend -> output (2,128,80,80)
__global__ void k_combine(float* __restrict__ out) {
    int idx = blockIdx.x*blockDim.x + threadIdx.x;
    const int total = NB*NC*FH*FW;
    if (idx >= total) return;
    int X = idx % FW; int t = idx / FW;
    int Y = t % FH; t /= FH;
    int c = t % NC; int b = t / NC;

    int dys[2], hh[2]; int ny = 0;
    if ((Y & 1) == 0) {
        dys[ny] = 0; hh[ny] = Y >> 1; ny++;
        if (Y >= 2) { dys[ny] = 2; hh[ny] = (Y-2) >> 1; ny++; }
    } else {
        dys[ny] = 1; hh[ny] = (Y-1) >> 1; ny++;
        if (Y <= 2*HS - 3) { dys[ny] = -1; hh[ny] = (Y+1) >> 1; ny++; }
    }
    int dxs[2], ww[2]; int nx = 0;
    if ((X & 1) == 0) {
        dxs[nx] = 0; ww[nx] = X >> 1; nx++;
        if (X >= 2) { dxs[nx] = 2; ww[nx] = (X-2) >> 1; nx++; }
    } else {
        dxs[nx] = 1; ww[nx] = (X-1) >> 1; nx++;
        if (X <= 2*HS - 3) { dxs[nx] = -1; ww[nx] = (X+1) >> 1; nx++; }
    }

    const float PI = 3.14159265358979323846f;
    float wl = 0.5f*(1.f + cosf(PI * (float)X        / (float)(FW-1)));
    float wr = 0.5f*(1.f + cosf(PI * (float)(FW-1-X) / (float)(FW-1)));

    float res = 0.f;
    for (int s = 0; s < 2; ++s) {
        const float* T = g_T + (size_t)(b*2 + s)*MROWS*NQ;
        float acc = 0.f;
        for (int iy = 0; iy < ny; ++iy) {
            for (int ix = 0; ix < nx; ++ix) {
                int m = c*16 + (dys[iy]+1)*4 + (dxs[ix]+1);
                acc += T[(size_t)m*NQ + hh[iy]*HS + ww[ix]];
            }
        }
        res += (s == 0 ? wl : wr) * 0.25f * acc;
    }
    out[idx] = res;
}

// ------------------------------------------------------------------ launcher
extern "C" void kernel_launch(void* const* d_in, const int* in_sizes, int n_in,
                              void* d_out, int out_size) {
    const float* left      = (const float*)d_in[0];
    const float* right     = (const float*)d_in[1];
    const float* mid       = (const float*)d_in[2];
    const float* raw_left  = (const float*)d_in[3];
    const float* raw_right = (const float*)d_in[4];
    float* outp = (float*)d_out;

    cudaFuncSetAttribute(k_gemm2t, cudaFuncAttributeMaxDynamicSharedMemorySize, G2_SMEM);

    int t1 = NB*3*NC*NQ;
    k_downsample<<<(t1+255)/256, 256>>>(left, right, mid);
    int t2 = NB*2*NQ;
    k_sumsq<<<(t2+127)/128, 128>>>();
    k_norm<<<(t2+127)/128, 128>>>();

    dim3 g1(NQ/64, NQ/64, NB*2);     // 25 x 25 x 4
    k_gemm1<<<g1, 256>>>();

    long long tp = (long long)NB*2*NQ*NQ;
    int nbElem = (int)((tp + 255) / 256);
    k_patchsum<<<nbElem, 256>>>();
    k_fuse1<<<nbElem, 256>>>();
    k_fuse2<<<nbElem, 256>>>();

    k_softmax_stats<<<dim3(NQ/64, NB*2), 256>>>();
    k_attnT<<<dim3(NQ/32, NQ/32, NB*2), dim3(32, 8)>>>();

    int tg = NB*2*MROWS*NQ;
    k_buildG<<<(tg+255)/256, 256>>>(raw_left, raw_right);

    dim3 g2(MROWS/128, (NQ+127)/128, NB*2);   // 16 x 13 x 4
    k_gemm2t<<<g2, 256, G2_SMEM>>>();

    int to = NB*NC*FH*FW;
    k_combine<<<(to+255)/256, 256>>>(outp);
}

// round 5
// speedup vs baseline: 2.7996x; 1.4167x over previous
#include <cuda_runtime.h>
#include <cuda_fp16.h>
#include <math.h>
#include <stdint.h>

// Problem constants
#define NB 2
#define NC 128
#define FH 80
#define FW 80
#define HS 40            // downsampled H=W
#define NQ 1600          // HS*HS
#define NEPS 0.1152f     // 1152 * EPS
#define SCL 10.0f
#define MROWS 2048       // NC * 16 offsets

// fp16 mma GEMM2 config: CTA 128x128, K-tile 32 halfs, 8 warps (warp tile 64x32)
#define KT 32
#define G2_SMEM 32768    // 2 buffers x (8KB A + 8KB B)

// Static scratch (allocation-free rule: __device__ globals)
__device__ float  g_ds[NB*3*NC*NQ];          // downsampled [b][img: 0=l,1=r,2=m][c][q]
__device__ float  g_E[NB*2*NQ];              // per-pixel channel sum of squares (l, r)
__device__ float  g_ninv[NB*2*NQ];           // 1/patch-norm
__device__ float  g_smax[NB*2*NQ];           // softmax max per (bs,p)
__device__ float  g_sinv[NB*2*NQ];           // softmax 1/sum per (bs,p)
__device__ float  g_bufA[NB*2*NQ*NQ];        // 41.9 MB ping
__device__ float  g_bufB[NB*2*NQ*NQ];        // 41.9 MB pong
__device__ __half g_Gh[NB*2*MROWS*NQ];       // 26 MB paste operand [bs][m][q] (half)
__device__ __half g_ATh[NB*2*NQ*NQ];         // 20.5 MB attnT [bs][p][q] (half)
__device__ float  g_T[NB*2*MROWS*NQ];        // 52.4 MB paste result [bs][m][p]

// ---------------------------------------------------------------- downsample
__global__ void k_downsample(const float* __restrict__ left,
                             const float* __restrict__ right,
                             const float* __restrict__ mid) {
    int idx = blockIdx.x * blockDim.x + threadIdx.x;
    const int total = NB*3*NC*NQ;
    if (idx >= total) return;
    int q = idx % NQ;
    int t = idx / NQ;
    int c = t % NC; t /= NC;
    int img = t % 3; int b = t / 3;
    const float* src = (img == 0) ? left : (img == 1 ? right : mid);
    int qh = q / HS, qw = q % HS;
    g_ds[idx] = src[(size_t)((b*NC + c)*FH + 2*qh)*FW + 2*qw];
}

// ------------------------------------------------- channel sum-of-squares (l,r)
__global__ void k_sumsq() {
    int idx = blockIdx.x*blockDim.x + threadIdx.x;
    const int total = NB*2*NQ;
    if (idx >= total) return;
    int q = idx % NQ; int t = idx / NQ;
    int s = t % 2; int b = t / 2;
    const float* p = g_ds + (size_t)(b*3 + s)*NC*NQ + q;
    float acc = 0.f;
    #pragma unroll 8
    for (int c = 0; c < NC; ++c) { float v = p[(size_t)c*NQ]; acc += v*v; }
    g_E[idx] = acc;
}

// -------------------------------------------------- patch norm
__global__ void k_norm() {
    int idx = blockIdx.x*blockDim.x + threadIdx.x;
    const int total = NB*2*NQ;
    if (idx >= total) return;
    int q = idx % NQ; int bs = idx / NQ;
    int qh = q/HS, qw = q%HS;
    float acc = NEPS;
    for (int di=-1; di<=1; ++di) {
        int h = qh+di; if (h < 0 || h >= HS) continue;
        for (int dj=-1; dj<=1; ++dj) {
            int w = qw+dj; if (w < 0 || w >= HS) continue;
            acc += g_E[bs*NQ + h*HS + w];
        }
    }
    g_ninv[idx] = rsqrtf(acc);
}

// ----------------------------- GEMM1 (fp32): PixCorr[q,p] = sum_c L[c,q]*M[c,p]
__global__ void k_gemm1() {
    int bs = blockIdx.z;
    int b = bs >> 1, s = bs & 1;
    const float* A  = g_ds + (size_t)(b*3 + s)*NC*NQ;
    const float* Bm = g_ds + (size_t)(b*3 + 2)*NC*NQ;
    float* Cout = g_bufA + (size_t)bs*NQ*NQ;
    __shared__ float As[16][64];
    __shared__ float Bs[16][64];
    int tx = threadIdx.x;
    int m0 = blockIdx.x*64, n0 = blockIdx.y*64;
    int lk = tx >> 4, lm = (tx & 15) * 4;
    int lr = tx >> 4, lc = tx & 15;
    float acc[4][4];
    #pragma unroll
    for (int i=0;i<4;i++)
        #pragma unroll
        for (int j=0;j<4;j++) acc[i][j] = 0.f;
    for (int k0 = 0; k0 < NC; k0 += 16) {
        *(float4*)&As[lk][lm] = *(const float4*)&A [(size_t)(k0+lk)*NQ + m0 + lm];
        *(float4*)&Bs[lk][lm] = *(const float4*)&Bm[(size_t)(k0+lk)*NQ + n0 + lm];
        __syncthreads();
        #pragma unroll
        for (int kk = 0; kk < 16; ++kk) {
            float4 av = *(const float4*)&As[kk][lr*4];
            float4 bv = *(const float4*)&Bs[kk][lc*4];
            float a[4] = {av.x, av.y, av.z, av.w};
            float bb[4] = {bv.x, bv.y, bv.z, bv.w};
            #pragma unroll
            for (int i=0;i<4;i++)
                #pragma unroll
                for (int j=0;j<4;j++) acc[i][j] += a[i]*bb[j];
        }
        __syncthreads();
    }
    #pragma unroll
    for (int i=0;i<4;i++) {
        float4 v = make_float4(acc[i][0],acc[i][1],acc[i][2],acc[i][3]);
        *(float4*)&Cout[(size_t)(m0+lr*4+i)*NQ + n0 + lc*4] = v;
    }
}

// -------- FUSED patchsum + fuse1:
// out[q][p] = sum_{e in {0,-1,+1}, flat bounds} ninv[q+e] * psum(q+e, p+e)
// psum(Q,P) = sum_{di,dj, 2D bounds} Cm[(Q+di*HS+dj)][(P+di*HS+dj)]
// (bufA -> bufB)
__global__ void k_psfuse() {
    long long idx = (long long)blockIdx.x*blockDim.x + threadIdx.x;
    const long long total = (long long)NB*2*NQ*NQ;
    if (idx >= total) return;
    int p = (int)(idx % NQ);
    long long t = idx / NQ;
    int q = (int)(t % NQ);
    int bs = (int)(t / NQ);
    const float* Cm = g_bufA + (size_t)bs*NQ*NQ;
    const float* ninv = g_ninv + bs*NQ;
    float acc = 0.f;
    const int es[3] = {0, -1, 1};
    #pragma unroll
    for (int ei = 0; ei < 3; ++ei) {
        int e = es[ei];
        int Q = q + e, P = p + e;
        if (Q < 0 || Q >= NQ || P < 0 || P >= NQ) continue;
        int Qh = Q/HS, Qw = Q - (Q/HS)*HS;
        int Ph = P/HS, Pw = P - (P/HS)*HS;
        float ps = 0.f;
        #pragma unroll
        for (int di=-1; di<=1; ++di) {
            if (Qh+di < 0 || Qh+di >= HS || Ph+di < 0 || Ph+di >= HS) continue;
            #pragma unroll
            for (int dj=-1; dj<=1; ++dj) {
                if (Qw+dj < 0 || Qw+dj >= HS || Pw+dj < 0 || Pw+dj >= HS) continue;
                int sh = di*HS + dj;
                ps += Cm[(Q+sh)*NQ + (P+sh)];
            }
        }
        acc += ps * ninv[Q];
    }
    g_bufB[idx] = acc;
}

__device__ __forceinline__ int tflat(int q) { return (q % HS) * HS + q / HS; }

// ---------------- fuse pass 2 (bufB -> bufA)
__global__ void k_fuse2() {
    long long idx = (long long)blockIdx.x*blockDim.x + threadIdx.x;
    const long long total = (long long)NB*2*NQ*NQ;
    if (idx >= total) return;
    int p = (int)(idx % NQ);
    long long t = idx / NQ;
    int q = (int)(t % NQ);
    int bs = (int)(t / NQ);
    const float* F = g_bufB + (size_t)bs*NQ*NQ;
    int a = tflat(q), bb = tflat(p);
    float acc = F[(size_t)q*NQ + p];
    if (a > 0    && bb > 0   ) acc += F[(size_t)tflat(a-1)*NQ + tflat(bb-1)];
    if (a < NQ-1 && bb < NQ-1) acc += F[(size_t)tflat(a+1)*NQ + tflat(bb+1)];
    g_bufA[idx] = acc;
}

// --------------- softmax stats: per (bs,p) max over q and 1/sum(exp) (reads bufA)
__global__ void k_softmax_stats() {
    int bs = blockIdx.y;
    int p0 = blockIdx.x * 64;
    const float* F = g_bufA + (size_t)bs*NQ*NQ;
    int px = threadIdx.x & 63;
    int qy = threadIdx.x >> 6;        // 0..3
    int p = p0 + px;
    __shared__ float red[4][64];
    float mx = -3.4e38f;
    for (int q = qy; q < NQ; q += 4) mx = fmaxf(mx, F[(size_t)q*NQ + p]);
    red[qy][px] = mx;
    __syncthreads();
    mx = fmaxf(fmaxf(red[0][px], red[1][px]), fmaxf(red[2][px], red[3][px]));
    __syncthreads();
    float sm = 0.f;
    for (int q = qy; q < NQ; q += 4) sm += __expf(SCL * (F[(size_t)q*NQ + p] - mx));
    red[qy][px] = sm;
    __syncthreads();
    if (qy == 0) {
        g_smax[bs*NQ + p] = mx;
        g_sinv[bs*NQ + p] = 1.0f / (red[0][px] + red[1][px] + red[2][px] + red[3][px]);
    }
}

// --------------- attnT: transposed, normalized attn as half (bufA -> g_ATh)
__global__ void k_attnT() {
    __shared__ float tile[32][33];
    int bs = blockIdx.z;
    int q0 = blockIdx.x * 32, p0 = blockIdx.y * 32;
    const float* F = g_bufA + (size_t)bs*NQ*NQ;
    __half* O = g_ATh + (size_t)bs*NQ*NQ;
    int tx = threadIdx.x, ty = threadIdx.y;  // 32 x 8
    for (int r = ty; r < 32; r += 8)
        tile[r][tx] = F[(size_t)(q0+r)*NQ + p0 + tx];
    __syncthreads();
    for (int r = ty; r < 32; r += 8) {
        int p = p0 + r;
        float e = __expf(SCL * (tile[tx][r] - g_smax[bs*NQ + p])) * g_sinv[bs*NQ + p];
        O[(size_t)p*NQ + q0 + tx] = __float2half_rn(e);
    }
}

// --------------- build paste operand G[bs][m][q] as half
__global__ void k_buildG(const float* __restrict__ raw_left,
                         const float* __restrict__ raw_right) {
    int idx = blockIdx.x*blockDim.x + threadIdx.x;
    const int total = NB*2*MROWS*NQ;
    if (idx >= total) return;
    int q = idx % NQ;
    int t = idx / NQ;
    int m = t % MROWS;
    int bs = t / MROWS;
    int b = bs >> 1, s = bs & 1;
    int c = m >> 4;
    int o = m & 15;
    int dy = (o >> 2) - 1, dx = (o & 3) - 1;
    int y = 2*(q/HS) + dy, x = 2*(q%HS) + dx;
    const float* raw = s ? raw_right : raw_left;
    float v = 0.f;
    if (y >= 0 && y < FH && x >= 0 && x < FW)
        v = raw[(size_t)((b*NC + c)*FH + y)*FW + x];
    g_Gh[idx] = __float2half_rn(v);
}

// ------------- GEMM2 (mma.sync fp16, f32 accum): T[m,p] = sum_q G[m,q] * attnT[p,q]
// CTA 128x128, K-tile 32 halfs (2 k-steps of 16), 8 warps (2m x 4n), warp tile 64x32.
// Fragment-permuted double-buffered smem; slot word order A=(a0,a2,a1,a3), B=(b0,b1).
__device__ __forceinline__ void mma_f16(float* c, uint32_t a0, uint32_t a1,
                                        uint32_t a2, uint32_t a3,
                                        uint32_t b0, uint32_t b1) {
    asm volatile(
        "mma.sync.aligned.m16n8k16.row.col.f32.f16.f16.f32 "
        "{%0,%1,%2,%3}, {%4,%5,%6,%7}, {%8,%9}, {%0,%1,%2,%3};"
        : "+f"(c[0]), "+f"(c[1]), "+f"(c[2]), "+f"(c[3])
        : "r"(a0), "r"(a1), "r"(a2), "r"(a3), "r"(b0), "r"(b1));
}

__global__ void __launch_bounds__(256) k_gemm2h() {
    extern __shared__ char smx[];
    const int bs = blockIdx.z;
    const __half* __restrict__ Gm = g_Gh  + (size_t)bs*MROWS*NQ;   // [m][q]
    const __half* __restrict__ Bm = g_ATh + (size_t)bs*NQ*NQ;      // [p][q]
    float* __restrict__ Tm = g_T + (size_t)bs*MROWS*NQ;
    const int m0 = blockIdx.x * 128, n0 = blockIdx.y * 128;
    const int t = threadIdx.x;
    const int lane = t & 31, wid = t >> 5;
    const int wm = wid & 1, wn = wid >> 1;      // warp grid 2(m) x 4(n)

    // producer assignment: row = t>>1 (0..127), k-chunk s = t&1 (16 halfs)
    const int prow = t >> 1, ps = t & 1;
    const int pmt = prow >> 4, prr = prow & 15;
    const int pgA = prr & 7;
    const int hwA = (prr >> 3) << 3;            // byte offset: 0 (a0,a2) or 8 (a1,a3)
    const int pnt = prow >> 3, pgB = prow & 7;
    const bool pBvalid = (n0 + prow) < NQ;

    uint32_t al[4], ah[4], bl[4], bh[4];

    float acc[4][4][4];
    #pragma unroll
    for (int i=0;i<4;i++)
        #pragma unroll
        for (int j=0;j<4;j++)
            #pragma unroll
            for (int k=0;k<4;k++) acc[i][j][k] = 0.f;

    // prime tile 0
    {
        const uint4* pa = (const uint4*)(Gm + (size_t)(m0+prow)*NQ + ps*16);
        uint4 lo = pa[0], hi = pa[1];
        al[0]=lo.x; al[1]=lo.y; al[2]=lo.z; al[3]=lo.w;
        ah[0]=hi.x; ah[1]=hi.y; ah[2]=hi.z; ah[3]=hi.w;
        if (pBvalid) {
            const uint4* pb = (const uint4*)(Bm + (size_t)(n0+prow)*NQ + ps*16);
            uint4 blo = pb[0], bhi = pb[1];
            bl[0]=blo.x; bl[1]=blo.y; bl[2]=blo.z; bl[3]=blo.w;
            bh[0]=bhi.x; bh[1]=bhi.y; bh[2]=bhi.z; bh[3]=bhi.w;
        } else {
            #pragma unroll
            for (int j=0;j<4;j++) { bl[j]=0u; bh[j]=0u; }
        }
    }

    const int NTILES = NQ / KT;   // 50
    for (int it = 0; it < NTILES; ++it) {
        char* base = smx + (it & 1) * 16384;
        char* Asl = base;             // 16 groups x 32 slots x 16B
        char* Bsl = base + 8192;      // 32 groups x 32 slots x 8B

        // scatter staged regs (4 STS.64 each operand)
        {
            char* aw = Asl + ((ps*8 + pmt)*32 + pgA*4) * 16 + hwA;
            char* bw = Bsl + ((ps*16 + pnt)*32 + pgB*4) * 8;
            #pragma unroll
            for (int j = 0; j < 4; ++j) {
                *(uint2*)(aw + j*16) = make_uint2(al[j], ah[j]);
                *(uint2*)(bw + j*8)  = make_uint2(bl[j], bh[j]);
            }
        }
        __syncthreads();

        // prefetch next tile (overlaps mma)
        if (it + 1 < NTILES) {
            int k0n = (it + 1) * KT;
            const uint4* pa = (const uint4*)(Gm + (size_t)(m0+prow)*NQ + k0n + ps*16);
            uint4 lo = pa[0], hi = pa[1];
            al[0]=lo.x; al[1]=lo.y; al[2]=lo.z; al[3]=lo.w;
            ah[0]=hi.x; ah[1]=hi.y; ah[2]=hi.z; ah[3]=hi.w;
            if (pBvalid) {
                const uint4* pb = (const uint4*)(Bm + (size_t)(n0+prow)*NQ + k0n + ps*16);
                uint4 blo = pb[0], bhi = pb[1];
                bl[0]=blo.x; bl[1]=blo.y; bl[2]=blo.z; bl[3]=blo.w;
                bh[0]=bhi.x; bh[1]=bhi.y; bh[2]=bhi.z; bh[3]=bhi.w;
            }
        }

        // consume 2 k-steps of 16
        #pragma unroll
        for (int s = 0; s < 2; ++s) {
            uint4 af[4]; uint2 bf[4];
            #pragma unroll
            for (int mt = 0; mt < 4; ++mt)
                af[mt] = *(const uint4*)(Asl + (((s*8 + wm*4 + mt)*32 + lane) * 16));
            #pragma unroll
            for (int nt = 0; nt < 4; ++nt)
                bf[nt] = *(const uint2*)(Bsl + (((s*16 + wn*4 + nt)*32 + lane) * 8));
            #pragma unroll
            for (int mt = 0; mt < 4; ++mt)
                #pragma unroll
                for (int nt = 0; nt < 4; ++nt)
                    mma_f16(acc[mt][nt], af[mt].x, af[mt].z, af[mt].y, af[mt].w,
                            bf[nt].x, bf[nt].y);
        }
    }

    // epilogue
    #pragma unroll
    for (int mt = 0; mt < 4; ++mt) {
        int m = m0 + wm*64 + mt*16 + (lane >> 2);
        #pragma unroll
        for (int nt = 0; nt < 4; ++nt) {
            int n = n0 + wn*32 + nt*8 + 2*(lane & 3);
            if (n < NQ) {
                *(float2*)&Tm[(size_t)m*NQ + n]     = make_float2(acc[mt][nt][0], acc[mt][nt][1]);
                *(float2*)&Tm[(size_t)(m+8)*NQ + n] = make_float2(acc[mt][nt][2], acc[mt][nt][3]);
            }
        }
    }
}

// ------------- gather epilogue + cosine-window blend -> output (2,128,80,80)
__global__ void k_combine(float* __restrict__ out) {
    int idx = blockIdx.x*blockDim.x + threadIdx.x;
    const int total = NB*NC*FH*FW;
    if (idx >= total) return;
    int X = idx % FW; int t = idx / FW;
    int Y = t % FH; t /= FH;
    int c = t % NC; int b = t / NC;

    int dys[2], hh[2]; int ny = 0;
    if ((Y & 1) == 0) {
        dys[ny] = 0; hh[ny] = Y >> 1; ny++;
        if (Y >= 2) { dys[ny] = 2; hh[ny] = (Y-2) >> 1; ny++; }
    } else {
        dys[ny] = 1; hh[ny] = (Y-1) >> 1; ny++;
        if (Y <= 2*HS - 3) { dys[ny] = -1; hh[ny] = (Y+1) >> 1; ny++; }
    }
    int dxs[2], ww[2]; int nx = 0;
    if ((X & 1) == 0) {
        dxs[nx] = 0; ww[nx] = X >> 1; nx++;
        if (X >= 2) { dxs[nx] = 2; ww[nx] = (X-2) >> 1; nx++; }
    } else {
        dxs[nx] = 1; ww[nx] = (X-1) >> 1; nx++;
        if (X <= 2*HS - 3) { dxs[nx] = -1; ww[nx] = (X+1) >> 1; nx++; }
    }

    const float PI = 3.14159265358979323846f;
    float wl = 0.5f*(1.f + cosf(PI * (float)X        / (float)(FW-1)));
    float wr = 0.5f*(1.f + cosf(PI * (float)(FW-1-X) / (float)(FW-1)));

    float res = 0.f;
    for (int s = 0; s < 2; ++s) {
        const float* T = g_T + (size_t)(b*2 + s)*MROWS*NQ;
        float acc = 0.f;
        for (int iy = 0; iy < ny; ++iy) {
            for (int ix = 0; ix < nx; ++ix) {
                int m = c*16 + (dys[iy]+1)*4 + (dxs[ix]+1);
                acc += T[(size_t)m*NQ + hh[iy]*HS + ww[ix]];
            }
        }
        res += (s == 0 ? wl : wr) * 0.25f * acc;
    }
    out[idx] = res;
}

// ------------------------------------------------------------------ launcher
extern "C" void kernel_launch(void* const* d_in, const int* in_sizes, int n_in,
                              void* d_out, int out_size) {
    const float* left      = (const float*)d_in[0];
    const float* right     = (const float*)d_in[1];
    const float* mid       = (const float*)d_in[2];
    const float* raw_left  = (const float*)d_in[3];
    const float* raw_right = (const float*)d_in[4];
    float* outp = (float*)d_out;

    cudaFuncSetAttribute(k_gemm2h, cudaFuncAttributeMaxDynamicSharedMemorySize, G2_SMEM);

    int t1 = NB*3*NC*NQ;
    k_downsample<<<(t1+255)/256, 256>>>(left, right, mid);
    int t2 = NB*2*NQ;
    k_sumsq<<<(t2+127)/128, 128>>>();
    k_norm<<<(t2+127)/128, 128>>>();

    dim3 g1(NQ/64, NQ/64, NB*2);     // 25 x 25 x 4
    k_gemm1<<<g1, 256>>>();

    long long tp = (long long)NB*2*NQ*NQ;
    int nbElem = (int)((tp + 255) / 256);
    k_psfuse<<<nbElem, 256>>>();
    k_fuse2<<<nbElem, 256>>>();

    k_softmax_stats<<<dim3(NQ/64, NB*2), 256>>>();
    k_attnT<<<dim3(NQ/32, NQ/32, NB*2), dim3(32, 8)>>>();

    int tg = NB*2*MROWS*NQ;
    k_buildG<<<(tg+255)/256, 256>>>(raw_left, raw_right);

    dim3 g2(MROWS/128, (NQ+127)/128, NB*2);   // 16 x 13 x 4
    k_gemm2h<<<g2, 256, G2_SMEM>>>();

    int to = NB*NC*FH*FW;
    k_combine<<<(to+255)/256, 256>>>(outp);
}